// round 11
// baseline (speedup 1.0000x reference)
#include <cuda_runtime.h>
#include <cstdint>

#define NBATCH 64
#define TSEQ   512
#define NIN    512
#define NH     1024
#define NG     4096          // 4*NH gate columns
#define NSTEPS 1024          // T * NUM_LAYERS
#define BH     (NBATCH * NH) // 65536 elements per (h or c) step
#define CS_OFF ((size_t)NSTEPS * BH)

#define NBLK   132           // persistent CTAs (< SM count, always co-resident)
#define NENG   (NBLK * 2)    // two 128-thread tile engines per CTA

// Split-K partial buffer: [12 slots][64 b][4096 cols].
// Slots 0..7  : Uw*h  K-chunks of 128 (K=1024), recomputed every step.
// Slots 8..11 : Ww*x_t K-chunks of 128 (K=512), recomputed on even steps only.
__device__ float g_part[12 * NBATCH * NG];

// Zero h for step 0 (device globals are zero-initialized; never written).
__device__ float g_h0[BH];

// Software grid barrier state (sense-free: monotonic generation counter).
__device__ unsigned g_cnt;
__device__ volatile unsigned g_gen;

__device__ __forceinline__ void bar_eng(int half) {
    // Named barrier per 128-thread tile engine (ids 1,2; id 0 = __syncthreads).
    asm volatile("bar.sync %0, 128;" :: "r"(half + 1) : "memory");
}

__device__ __forceinline__ void gridbar() {
    __syncthreads();
    if (threadIdx.x == 0) {
        unsigned my = g_gen;          // must read BEFORE arriving
        __threadfence();              // publish this block's global writes
        if (atomicAdd(&g_cnt, 1u) == (unsigned)NBLK - 1u) {
            g_cnt = 0;                // safe: others spin on g_gen, not g_cnt
            __threadfence();
            atomicAdd((unsigned*)&g_gen, 1u);
        } else {
            while (g_gen == my) __nanosleep(32);
        }
        __threadfence();              // acquire other blocks' writes
    }
    __syncthreads();
}

__device__ __forceinline__ float sigm(float v) { return 1.f / (1.f + __expf(-v)); }

__global__ void __launch_bounds__(256, 1) lstm_persist(
    const float* __restrict__ x,  const float* __restrict__ Ww,
    const float* __restrict__ bw, const float* __restrict__ Uw,
    const float* __restrict__ bu, float* __restrict__ out)
{
    __shared__ float hs[2][16][68];    // [engine][k][b], 68%4==0 keeps 16B align
    __shared__ float Us[2][16][132];   // [engine][k][c]

    const int tid  = threadIdx.x;
    const int half = tid >> 7;                  // which tile engine (0/1)
    const int etid = tid & 127;                 // thread id within engine
    const int eng  = blockIdx.x * 2 + half;     // global engine id (0..263)
    const int gtid = blockIdx.x * 256 + tid;    // for phase B

    // Load mapping: activations 64 rows x 16 k; weights 128 cols x 16 k.
    const int hb  = etid & 63;
    const int hk  = (etid >> 6) * 8;
    // Micro-tile: 8 batch rows x 8 cols, columns {cl4..cl4+3, cl4+64..cl4+67}
    // (lane stride 4 words -> conflict-free LDS.128 on Us).
    const int b0  = (etid >> 4) * 8 & 63;
    const int cl4 = (etid & 15) * 4;

    for (int s = 0; s < NSTEPS; ++s) {
        const int t = s >> 1;
        const int ntiles = ((s & 1) == 0) ? 384 : 256;   // 12 or 8 slots x 32 colblocks
        const float* hprev = (s == 0) ? g_h0 : (out + (size_t)(s - 1) * BH);

        // ------------------ Phase A: split-K GEMM tiles ------------------
        for (int tile = eng; tile < ntiles; tile += NENG) {
            const int slot = tile >> 5;
            const int c0   = (tile & 31) * 128;

            const float* kmat; const float* act;
            int kstride, astride, koff;
            if (slot < 8) {
                kmat = Uw; kstride = NH;  act = hprev;               astride = NH;         koff = slot * 128;
            } else {
                kmat = Ww; kstride = NIN; act = x + (size_t)t * NIN; astride = TSEQ * NIN; koff = (slot - 8) * 128;
            }

            const float* ap = act  + (size_t)hb * astride + koff + hk;
            const float* up = kmat + (size_t)(c0 + etid) * kstride + koff;

            float acc[8][8];
#pragma unroll
            for (int i = 0; i < 8; i++)
#pragma unroll
                for (int j = 0; j < 8; j++) acc[i][j] = 0.f;

            // Prefetch K-chunk 0
            float4 h0 = *(const float4*)(ap);
            float4 h1 = *(const float4*)(ap + 4);
            float4 u0 = *(const float4*)(up);
            float4 u1 = *(const float4*)(up + 4);
            float4 u2 = *(const float4*)(up + 8);
            float4 u3 = *(const float4*)(up + 12);

            for (int ks = 0; ks < 8; ++ks) {
                bar_eng(half);   // previous iteration's readers done
                hs[half][hk+0][hb] = h0.x; hs[half][hk+1][hb] = h0.y;
                hs[half][hk+2][hb] = h0.z; hs[half][hk+3][hb] = h0.w;
                hs[half][hk+4][hb] = h1.x; hs[half][hk+5][hb] = h1.y;
                hs[half][hk+6][hb] = h1.z; hs[half][hk+7][hb] = h1.w;
                Us[half][0][etid]  = u0.x; Us[half][1][etid]  = u0.y;
                Us[half][2][etid]  = u0.z; Us[half][3][etid]  = u0.w;
                Us[half][4][etid]  = u1.x; Us[half][5][etid]  = u1.y;
                Us[half][6][etid]  = u1.z; Us[half][7][etid]  = u1.w;
                Us[half][8][etid]  = u2.x; Us[half][9][etid]  = u2.y;
                Us[half][10][etid] = u2.z; Us[half][11][etid] = u2.w;
                Us[half][12][etid] = u3.x; Us[half][13][etid] = u3.y;
                Us[half][14][etid] = u3.z; Us[half][15][etid] = u3.w;
                bar_eng(half);

                if (ks < 7) {     // prefetch next K-chunk; hidden under compute
                    ap += 16; up += 16;
                    h0 = *(const float4*)(ap);
                    h1 = *(const float4*)(ap + 4);
                    u0 = *(const float4*)(up);
                    u1 = *(const float4*)(up + 4);
                    u2 = *(const float4*)(up + 8);
                    u3 = *(const float4*)(up + 12);
                }

#pragma unroll
                for (int kk = 0; kk < 16; ++kk) {
                    float ra[8], rb[8];
                    *(float4*)&ra[0] = *(const float4*)&hs[half][kk][b0];
                    *(float4*)&ra[4] = *(const float4*)&hs[half][kk][b0 + 4];
                    *(float4*)&rb[0] = *(const float4*)&Us[half][kk][cl4];
                    *(float4*)&rb[4] = *(const float4*)&Us[half][kk][cl4 + 64];
#pragma unroll
                    for (int i = 0; i < 8; i++)
#pragma unroll
                        for (int j = 0; j < 8; j++) acc[i][j] += ra[i] * rb[j];
                }
            }

#pragma unroll
            for (int i = 0; i < 8; i++) {
                float* o = g_part + (size_t)(slot * NBATCH + b0 + i) * NG + c0;
                *(float4*)(o + cl4)      = make_float4(acc[i][0], acc[i][1], acc[i][2], acc[i][3]);
                *(float4*)(o + cl4 + 64) = make_float4(acc[i][4], acc[i][5], acc[i][6], acc[i][7]);
            }
        }

        gridbar();   // all g_part slots visible

        // ------------------ Phase B: reduce + LSTM cell ------------------
        for (int idx = gtid; idx < BH; idx += NBLK * 256) {
            const int b = idx >> 10;
            const int j = idx & 1023;

            float g[4];
#pragma unroll
            for (int gi = 0; gi < 4; ++gi) {
                const int c = j + gi * NH;
                float v = bw[c] + bu[c];
                const float* p = g_part + (size_t)b * NG + c;
#pragma unroll
                for (int sl = 0; sl < 12; ++sl) v += p[(size_t)sl * (NBATCH * NG)];
                g[gi] = v;
            }

            const float cprev = (s == 0) ? 0.f : out[CS_OFF + (size_t)(s - 1) * BH + idx];
            const float ig = sigm(g[0]);
            const float fg = sigm(g[1]);
            const float gg = tanhf(g[2]);
            const float og = sigm(g[3]);
            const float cn = fmaf(cprev, fg, ig * gg);
            const float hn = og * tanhf(cn);

            out[(size_t)s * BH + idx]          = hn;   // hs[s]
            out[CS_OFF + (size_t)s * BH + idx] = cn;   // cs[s]
        }

        gridbar();   // h[s]/c[s] visible to next step's phase A
    }
}

extern "C" void kernel_launch(void* const* d_in, const int* in_sizes, int n_in,
                              void* d_out, int out_size)
{
    (void)in_sizes; (void)n_in; (void)out_size;
    const float* x  = (const float*)d_in[0];
    const float* Ww = (const float*)d_in[1];
    const float* bw = (const float*)d_in[2];
    const float* Uw = (const float*)d_in[3];
    const float* bu = (const float*)d_in[4];
    float* out = (float*)d_out;

    // Single persistent kernel: 1 graph node (fixes the 4 MB graph-upload
    // teardown violation) and removes 2048 launch/graph-node latencies.
    lstm_persist<<<NBLK, 256>>>(x, Ww, bw, Uw, bu, out);
}

// round 14
// speedup vs baseline: 1.1393x; 1.1393x over previous
#include <cuda_runtime.h>
#include <cstdint>

#define NBATCH 64
#define TSEQ   512
#define NIN    512
#define NH     1024
#define NG     4096          // 4*NH gate columns
#define NSTEPS 1024          // T * NUM_LAYERS
#define BH     (NBATCH * NH) // 65536 elements per (h or c) step
#define CS_OFF ((size_t)NSTEPS * BH)

#define NBLK   148           // persistent CTAs (<= SM count, co-resident)
#define NENG   (NBLK * 2)    // 296 tile engines (128 threads each)

// Split-K partial buffer: [12 slots][64 b][4096 cols].
// Slots 0..7  : Uw*h  K-chunks of 128 (K=1024), recomputed every step.
// Slots 8..11 : Ww*x_t K-chunks of 128 (K=512), recomputed on even steps only.
__device__ float g_part[12 * NBATCH * NG];

// Zero h for step 0 (device globals zero-initialized; never written).
__device__ float g_h0[BH];

// Software grid barrier (monotonic generation counter).
__device__ unsigned g_cnt;
__device__ volatile unsigned g_gen;

__device__ __forceinline__ void bar_eng(int half) {
    asm volatile("bar.sync %0, 128;" :: "r"(half + 1) : "memory");
}

__device__ __forceinline__ void gridbar() {
    __syncthreads();
    if (threadIdx.x == 0) {
        unsigned my = g_gen;          // read BEFORE arriving
        __threadfence();              // publish this block's global writes
        if (atomicAdd(&g_cnt, 1u) == (unsigned)NBLK - 1u) {
            g_cnt = 0;                // safe: others spin on g_gen
            __threadfence();
            atomicAdd((unsigned*)&g_gen, 1u);
        } else {
            while (g_gen == my) __nanosleep(16);
        }
        __threadfence();              // acquire other blocks' writes
    }
    __syncthreads();
}

// Packed dual-FMA: d = a*b + d on two f32 lanes in one instruction.
// ptxas never emits FFMA2 from C++ (SASS_QUICKREF); PTX fma.rn.f32x2 only.
__device__ __forceinline__ void ffma2(float2& d, const float2& a, const float2& b) {
    unsigned long long dd = *(const unsigned long long*)&d;
    asm("fma.rn.f32x2 %0, %1, %2, %0;"
        : "+l"(dd)
        : "l"(*(const unsigned long long*)&a),
          "l"(*(const unsigned long long*)&b));
    d = *(float2*)&dd;
}

__device__ __forceinline__ float sigm(float v) { return 1.f / (1.f + __expf(-v)); }

__global__ void __launch_bounds__(256, 1) lstm_persist(
    const float* __restrict__ x,  const float* __restrict__ Ww,
    const float* __restrict__ bw, const float* __restrict__ Uw,
    const float* __restrict__ bu, float* __restrict__ out)
{
    // hsd: activations duplicated per element -> LDS.64 yields (a,a) pairs,
    //      feeding fma.rn.f32x2 with zero packing instructions.
    __shared__ float hsd[2][16][132];   // [engine][k][2*b (+pad)]
    __shared__ float Us[2][16][132];    // [engine][k][c (+pad)]

    const int tid  = threadIdx.x;
    const int half = tid >> 7;                  // tile engine in CTA (0/1)
    const int etid = tid & 127;
    const int eng  = blockIdx.x * 2 + half;     // global engine id (0..295)
    const int gtid = blockIdx.x * 256 + tid;    // for phase B

    // Load mapping: activations 64 rows x 16 k; weights 128 cols x 16 k.
    const int hb  = etid & 63;
    const int hk  = (etid >> 6) * 8;
    // Micro-tile: 8 batch rows x 8 cols, columns {cl4..+3, cl4+64..+67}.
    const int b0  = (etid >> 4) * 8 & 63;
    const int cl4 = (etid & 15) * 4;

    for (int s = 0; s < NSTEPS; ++s) {
        const int t = s >> 1;
        const int even = ((s & 1) == 0);
        const float* hprev = (s == 0) ? g_h0 : (out + (size_t)(s - 1) * BH);

        // Static tile->engine map. Tiles: slot*32 + colblock.
        // Odd steps : 256 tiles, 1 per engine (engines 256+ idle).
        // Even steps: 384 tiles; engines 0..295 take 1 each, overflow tiles
        //   296..383 go to even engines of CTAs 0..87 -> worst CTA = 3 tiles
        //   (12.3us instead of 2 full rounds = 16.4us).
        int tiles[2]; int nt = 0;
        if (even) {
            tiles[nt++] = eng;
            if (!(eng & 1) && (eng >> 1) < 88) tiles[nt++] = 296 + (eng >> 1);
        } else if (eng < 256) {
            tiles[nt++] = eng;
        }

        // ------------------ Phase A: split-K GEMM tiles ------------------
        for (int q = 0; q < nt; ++q) {
            const int tile = tiles[q];
            const int slot = tile >> 5;
            const int c0   = (tile & 31) * 128;

            const float* kmat; const float* act;
            int kstride, astride, koff;
            if (slot < 8) {
                kmat = Uw; kstride = NH;  act = hprev;               astride = NH;         koff = slot * 128;
            } else {
                kmat = Ww; kstride = NIN; act = x + (size_t)t * NIN; astride = TSEQ * NIN; koff = (slot - 8) * 128;
            }

            const float* ap = act  + (size_t)hb * astride + koff + hk;
            const float* up = kmat + (size_t)(c0 + etid) * kstride + koff;

            float2 acc2[8][4];
#pragma unroll
            for (int i = 0; i < 8; i++)
#pragma unroll
                for (int j = 0; j < 4; j++) acc2[i][j] = make_float2(0.f, 0.f);

            // Prefetch K-chunk 0
            float4 h0 = *(const float4*)(ap);
            float4 h1 = *(const float4*)(ap + 4);
            float4 u0 = *(const float4*)(up);
            float4 u1 = *(const float4*)(up + 4);
            float4 u2 = *(const float4*)(up + 8);
            float4 u3 = *(const float4*)(up + 12);

            for (int ks = 0; ks < 8; ++ks) {
                bar_eng(half);   // previous iteration's readers done
                // activations: duplicated (v,v) pairs via STS.64
                *(float2*)&hsd[half][hk+0][2*hb] = make_float2(h0.x, h0.x);
                *(float2*)&hsd[half][hk+1][2*hb] = make_float2(h0.y, h0.y);
                *(float2*)&hsd[half][hk+2][2*hb] = make_float2(h0.z, h0.z);
                *(float2*)&hsd[half][hk+3][2*hb] = make_float2(h0.w, h0.w);
                *(float2*)&hsd[half][hk+4][2*hb] = make_float2(h1.x, h1.x);
                *(float2*)&hsd[half][hk+5][2*hb] = make_float2(h1.y, h1.y);
                *(float2*)&hsd[half][hk+6][2*hb] = make_float2(h1.z, h1.z);
                *(float2*)&hsd[half][hk+7][2*hb] = make_float2(h1.w, h1.w);
                Us[half][0][etid]  = u0.x; Us[half][1][etid]  = u0.y;
                Us[half][2][etid]  = u0.z; Us[half][3][etid]  = u0.w;
                Us[half][4][etid]  = u1.x; Us[half][5][etid]  = u1.y;
                Us[half][6][etid]  = u1.z; Us[half][7][etid]  = u1.w;
                Us[half][8][etid]  = u2.x; Us[half][9][etid]  = u2.y;
                Us[half][10][etid] = u2.z; Us[half][11][etid] = u2.w;
                Us[half][12][etid] = u3.x; Us[half][13][etid] = u3.y;
                Us[half][14][etid] = u3.z; Us[half][15][etid] = u3.w;
                bar_eng(half);

                if (ks < 7) {     // prefetch next K-chunk under compute
                    ap += 16; up += 16;
                    h0 = *(const float4*)(ap);
                    h1 = *(const float4*)(ap + 4);
                    u0 = *(const float4*)(up);
                    u1 = *(const float4*)(up + 4);
                    u2 = *(const float4*)(up + 8);
                    u3 = *(const float4*)(up + 12);
                }

#pragma unroll
                for (int kk = 0; kk < 16; ++kk) {
                    float4 w01 = *(const float4*)&Us[half][kk][cl4];
                    float4 w23 = *(const float4*)&Us[half][kk][cl4 + 64];
                    float2 bb0 = make_float2(w01.x, w01.y);
                    float2 bb1 = make_float2(w01.z, w01.w);
                    float2 bb2 = make_float2(w23.x, w23.y);
                    float2 bb3 = make_float2(w23.z, w23.w);
#pragma unroll
                    for (int i = 0; i < 8; ++i) {
                        float2 aa = *(const float2*)&hsd[half][kk][2*(b0 + i)];
                        ffma2(acc2[i][0], aa, bb0);
                        ffma2(acc2[i][1], aa, bb1);
                        ffma2(acc2[i][2], aa, bb2);
                        ffma2(acc2[i][3], aa, bb3);
                    }
                }
            }

#pragma unroll
            for (int i = 0; i < 8; i++) {
                float* o = g_part + (size_t)(slot * NBATCH + b0 + i) * NG + c0;
                *(float4*)(o + cl4)      = make_float4(acc2[i][0].x, acc2[i][0].y,
                                                       acc2[i][1].x, acc2[i][1].y);
                *(float4*)(o + cl4 + 64) = make_float4(acc2[i][2].x, acc2[i][2].y,
                                                       acc2[i][3].x, acc2[i][3].y);
            }
        }

        gridbar();   // all g_part slots visible

        // ------------------ Phase B: reduce + LSTM cell ------------------
        for (int idx = gtid; idx < BH; idx += NBLK * 256) {
            const int b = idx >> 10;
            const int j = idx & 1023;

            float g[4];
#pragma unroll
            for (int gi = 0; gi < 4; ++gi) {
                const int c = j + gi * NH;
                float v = bw[c] + bu[c];
                const float* p = g_part + (size_t)b * NG + c;
#pragma unroll
                for (int sl = 0; sl < 12; ++sl) v += p[(size_t)sl * (NBATCH * NG)];
                g[gi] = v;
            }

            const float cprev = (s == 0) ? 0.f : out[CS_OFF + (size_t)(s - 1) * BH + idx];
            const float ig = sigm(g[0]);
            const float fg = sigm(g[1]);
            const float gg = tanhf(g[2]);
            const float og = sigm(g[3]);
            const float cn = fmaf(cprev, fg, ig * gg);
            const float hn = og * tanhf(cn);

            out[(size_t)s * BH + idx]          = hn;   // hs[s]
            out[CS_OFF + (size_t)s * BH + idx] = cn;   // cs[s]
        }

        gridbar();   // h[s]/c[s] visible to next step's phase A
    }
}

extern "C" void kernel_launch(void* const* d_in, const int* in_sizes, int n_in,
                              void* d_out, int out_size)
{
    (void)in_sizes; (void)n_in; (void)out_size;
    const float* x  = (const float*)d_in[0];
    const float* Ww = (const float*)d_in[1];
    const float* bw = (const float*)d_in[2];
    const float* Uw = (const float*)d_in[3];
    const float* bu = (const float*)d_in[4];
    float* out = (float*)d_out;

    lstm_persist<<<NBLK, 256>>>(x, Ww, bw, Uw, bu, out);
}